// round 1
// baseline (speedup 1.0000x reference)
#include <cuda_runtime.h>
#include <cstdint>

// ---------------------------------------------------------------------------
// Cross-modal attention, aq=1, softmax=1, sigmoid=0 (fixed by setup_inputs).
// B=16, N=4096, Kq=64, C=1024, H=8, d=128. Output (16,64,1024) fp32.
//
// Reassociated algorithm (saves ~2x FLOPs vs naive projection):
//   1) q    = aud @ Wq^T                      (1024 x 1024 x 1024)        NT
//   2) qt_bh = Q_bh @ Wk_h                    (64 x 1024 x 128)  x128     NN
//   3) sc_b  = qt_b @ img_b^T * scale         (512 x 4096 x 1024) x16     NT
//   4) softmax rows of sc (8192 rows x 4096)
//   5) t_b   = sc_b @ img_b                   (512 x 1024 x 4096) x16     NN
//   6) out_bh = t_bh @ Wv_h^T                 (64 x 128 x 1024)  x128     NT
// ---------------------------------------------------------------------------

__device__ __align__(16) float g_q[16 * 64 * 1024];        //   4 MB
__device__ __align__(16) float g_qt[16 * 8 * 64 * 1024];   //  32 MB
__device__ __align__(16) float g_sc[16 * 512 * 4096];      // 128 MB
__device__ __align__(16) float g_t[16 * 8 * 64 * 1024];    //  32 MB

template <int BM, int BN, int BK, int TM, int TN, bool TRANSB>
__global__ __launch_bounds__((BM / TM) * (BN / TN))
void sgemm_kernel(const float* __restrict__ Ag, const float* __restrict__ Bg,
                  float* __restrict__ Cg,
                  int M, int N, int K, int lda, int ldb, int ldc,
                  long aOff1, long aOff2, long bOff1, long bOff2,
                  long cOff1, long cOff2, int Z2, float alpha) {
    constexpr int THREADS = (BM / TM) * (BN / TN);
    const int z = blockIdx.z;
    const int z1 = z / Z2;
    const int z2 = z - z1 * Z2;
    const float* A = Ag + (long)z1 * aOff1 + (long)z2 * aOff2;
    const float* B = Bg + (long)z1 * bOff1 + (long)z2 * bOff2;
    float* C = Cg + (long)z1 * cOff1 + (long)z2 * cOff2;

    __shared__ __align__(16) float As[BK][BM];
    __shared__ __align__(16) float Bs[BK][BN];

    const int tid = threadIdx.x;
    const int m0 = blockIdx.y * BM;
    const int n0 = blockIdx.x * BN;
    const int tm0 = (tid / (BN / TN)) * TM;
    const int tn0 = (tid % (BN / TN)) * TN;

    float acc[TM][TN] = {};

    constexpr int KV = BK / 4;  // float4's per k-slice
    constexpr int A_PER = (BM * KV) / THREADS;
    static_assert(A_PER * THREADS == BM * KV, "A tile load mismatch");

    for (int kt = 0; kt < K; kt += BK) {
        // --- load A tile (BM x BK), store transposed As[k][m] ---
        #pragma unroll
        for (int i = 0; i < A_PER; i++) {
            int idx = tid + i * THREADS;
            int row = idx / KV;
            int cv = idx - row * KV;
            float4 v = *reinterpret_cast<const float4*>(
                A + (long)(m0 + row) * lda + kt + cv * 4);
            As[cv * 4 + 0][row] = v.x;
            As[cv * 4 + 1][row] = v.y;
            As[cv * 4 + 2][row] = v.z;
            As[cv * 4 + 3][row] = v.w;
        }
        // --- load B tile ---
        if constexpr (TRANSB) {
            // B is N x K: tile BN x BK, store transposed Bs[k][n]
            constexpr int B_PER = (BN * KV) / THREADS;
            static_assert(B_PER * THREADS == BN * KV, "B tile load mismatch");
            #pragma unroll
            for (int i = 0; i < B_PER; i++) {
                int idx = tid + i * THREADS;
                int row = idx / KV;
                int cv = idx - row * KV;
                float4 v = *reinterpret_cast<const float4*>(
                    B + (long)(n0 + row) * ldb + kt + cv * 4);
                Bs[cv * 4 + 0][row] = v.x;
                Bs[cv * 4 + 1][row] = v.y;
                Bs[cv * 4 + 2][row] = v.z;
                Bs[cv * 4 + 3][row] = v.w;
            }
        } else {
            // B is K x N: tile BK x BN, direct Bs[k][n]
            constexpr int NV = BN / 4;
            constexpr int B_PER = (BK * NV) / THREADS;
            static_assert(B_PER * THREADS == BK * NV, "B tile load mismatch");
            #pragma unroll
            for (int i = 0; i < B_PER; i++) {
                int idx = tid + i * THREADS;
                int row = idx / NV;
                int cv = idx - row * NV;
                float4 v = *reinterpret_cast<const float4*>(
                    B + (long)(kt + row) * ldb + n0 + cv * 4);
                *reinterpret_cast<float4*>(&Bs[row][cv * 4]) = v;
            }
        }
        __syncthreads();

        #pragma unroll
        for (int kk = 0; kk < BK; kk++) {
            float ra[TM], rb[TN];
            #pragma unroll
            for (int i = 0; i < TM / 4; i++)
                *reinterpret_cast<float4*>(&ra[i * 4]) =
                    *reinterpret_cast<const float4*>(&As[kk][tm0 + i * 4]);
            #pragma unroll
            for (int j = 0; j < TN / 4; j++)
                *reinterpret_cast<float4*>(&rb[j * 4]) =
                    *reinterpret_cast<const float4*>(&Bs[kk][tn0 + j * 4]);
            #pragma unroll
            for (int i = 0; i < TM; i++)
                #pragma unroll
                for (int j = 0; j < TN; j++)
                    acc[i][j] = fmaf(ra[i], rb[j], acc[i][j]);
        }
        __syncthreads();
    }

    #pragma unroll
    for (int i = 0; i < TM; i++) {
        #pragma unroll
        for (int j = 0; j < TN / 4; j++) {
            float4 v;
            v.x = alpha * acc[i][j * 4 + 0];
            v.y = alpha * acc[i][j * 4 + 1];
            v.z = alpha * acc[i][j * 4 + 2];
            v.w = alpha * acc[i][j * 4 + 3];
            *reinterpret_cast<float4*>(
                C + (long)(m0 + tm0 + i) * ldc + n0 + tn0 + j * 4) = v;
        }
    }
}

// One block per row of 4096; whole row lives in 16 registers/thread.
__global__ __launch_bounds__(256) void softmax4096_kernel(float* __restrict__ S) {
    float* row = S + (size_t)blockIdx.x * 4096;
    const int tid = threadIdx.x;
    __shared__ float red[8];

    float4 v[4];
    float maxv = -3.4e38f;
    #pragma unroll
    for (int i = 0; i < 4; i++) {
        v[i] = reinterpret_cast<const float4*>(row)[tid + i * 256];
        maxv = fmaxf(maxv, fmaxf(fmaxf(v[i].x, v[i].y), fmaxf(v[i].z, v[i].w)));
    }
    #pragma unroll
    for (int o = 16; o > 0; o >>= 1)
        maxv = fmaxf(maxv, __shfl_xor_sync(0xffffffffu, maxv, o));
    if ((tid & 31) == 0) red[tid >> 5] = maxv;
    __syncthreads();
    float bm = red[0];
    #pragma unroll
    for (int i = 1; i < 8; i++) bm = fmaxf(bm, red[i]);

    float sum = 0.f;
    #pragma unroll
    for (int i = 0; i < 4; i++) {
        v[i].x = __expf(v[i].x - bm);
        v[i].y = __expf(v[i].y - bm);
        v[i].z = __expf(v[i].z - bm);
        v[i].w = __expf(v[i].w - bm);
        sum += (v[i].x + v[i].y) + (v[i].z + v[i].w);
    }
    __syncthreads();  // red reuse
    #pragma unroll
    for (int o = 16; o > 0; o >>= 1) sum += __shfl_xor_sync(0xffffffffu, sum, o);
    if ((tid & 31) == 0) red[tid >> 5] = sum;
    __syncthreads();
    float tot = 0.f;
    #pragma unroll
    for (int i = 0; i < 8; i++) tot += red[i];
    const float inv = 1.0f / tot;
    #pragma unroll
    for (int i = 0; i < 4; i++) {
        v[i].x *= inv; v[i].y *= inv; v[i].z *= inv; v[i].w *= inv;
        reinterpret_cast<float4*>(row)[tid + i * 256] = v[i];
    }
}

extern "C" void kernel_launch(void* const* d_in, const int* in_sizes, int n_in,
                              void* d_out, int out_size) {
    const float* img = (const float*)d_in[0];  // (16,4096,1024)
    const float* aud = (const float*)d_in[1];  // (16,64,1024)
    const float* Wq = (const float*)d_in[2];   // (1024,1024)
    const float* Wk = (const float*)d_in[3];
    const float* Wv = (const float*)d_in[4];
    float* out = (float*)d_out;                // (16,64,1024)

    float *q, *qt, *sc, *t;
    cudaGetSymbolAddress((void**)&q, g_q);
    cudaGetSymbolAddress((void**)&qt, g_qt);
    cudaGetSymbolAddress((void**)&sc, g_sc);
    cudaGetSymbolAddress((void**)&t, g_t);

    const float scale = 0.08838834764831845f;  // (1024/8)^-0.5

    // 1) q = aud @ Wq^T : M=1024 (16*64 flattened), N=1024, K=1024
    sgemm_kernel<128, 128, 16, 8, 8, true><<<dim3(8, 8, 1), 256>>>(
        aud, Wq, q, 1024, 1024, 1024, 1024, 1024, 1024,
        0, 0, 0, 0, 0, 0, 1, 1.0f);

    // 2) qt[b,h] = Q_bh @ Wk_h : M=64, N=1024, K=128, z = b*8+h
    sgemm_kernel<64, 64, 16, 4, 4, false><<<dim3(16, 1, 128), 256>>>(
        q, Wk, qt, 64, 1024, 128, 1024, 1024, 1024,
        65536, 128, 0, 131072, 524288, 65536, 8, 1.0f);

    // 3) sc_b = qt_b @ img_b^T * scale : M=512, N=4096, K=1024, z = b
    sgemm_kernel<128, 128, 16, 8, 8, true><<<dim3(32, 4, 16), 256>>>(
        qt, img, sc, 512, 4096, 1024, 1024, 1024, 4096,
        524288, 0, 4194304, 0, 2097152, 0, 1, scale);

    // 4) softmax over the 4096-wide rows (16*512 rows)
    softmax4096_kernel<<<16 * 512, 256>>>(sc);

    // 5) t_b = P_b @ img_b : M=512, N=1024, K=4096, z = b
    sgemm_kernel<128, 128, 16, 8, 8, false><<<dim3(8, 4, 16), 256>>>(
        sc, img, t, 512, 1024, 4096, 4096, 1024, 1024,
        2097152, 0, 4194304, 0, 524288, 0, 1, 1.0f);

    // 6) out[b,:,h*128:(h+1)*128] = t_bh @ Wv_h^T : M=64, N=128, K=1024
    sgemm_kernel<64, 64, 16, 4, 4, true><<<dim3(2, 1, 128), 256>>>(
        t, Wv, out, 64, 128, 1024, 1024, 1024, 1024,
        524288, 65536, 0, 131072, 65536, 128, 8, 1.0f);
}

// round 5
// speedup vs baseline: 2.8153x; 2.8153x over previous
#include <cuda_runtime.h>
#include <cstdint>

// ---------------------------------------------------------------------------
// Cross-modal attention, aq=1, softmax=1, sigmoid=0.
// B=16, N=4096, Kq=64, C=1024, H=8, d=128. Output (16,64,1024) fp32.
//
// Reassociated algorithm:
//   1) q    = aud @ Wq^T                  (1024 x 1024 x 1024)  NT   [tf32 mma]
//   2) qt_bh = Q_bh @ Wk_h                (64 x 1024 x 128) x128 NN  [fp32]
//   3) sc_b  = qt_b @ img_b^T * scale     (512 x 4096 x 1024) x16 NT [tf32 mma]
//   4) softmax rows of sc (8192 rows x 4096)
//   5) t_b   = sc_b @ img_b               (512 x 1024 x 4096) x16 NN [tf32 mma]
//   6) out_bh = t_bh @ Wv_h^T             (64 x 128 x 1024) x128 NT  [fp32]
// ---------------------------------------------------------------------------

__device__ __align__(16) float g_q[16 * 64 * 1024];        //   4 MB
__device__ __align__(16) float g_qt[16 * 8 * 64 * 1024];   //  32 MB
__device__ __align__(16) float g_sc[16 * 512 * 4096];      // 128 MB
__device__ __align__(16) float g_t[16 * 8 * 64 * 1024];    //  32 MB

__device__ __forceinline__ uint32_t f2tf32(float x) {
    uint32_t r;
    asm("cvt.rna.tf32.f32 %0, %1;" : "=r"(r) : "f"(x));
    return r;
}

// ======================= TF32 tensor-core GEMM =============================
// C[M,N] = alpha * A[M,K] * op(B), A row-major (lda = K-stride).
// TRANSB: B is N x K row-major (NT). else: B is K x N row-major (NN).
// Block tile 128x128x32, 8 warps (4x2), warp tile 32x64, mma m16n8k8.
template <bool TRANSB>
__global__ __launch_bounds__(256)
void tf32_gemm_kernel(const float* __restrict__ Ag, const float* __restrict__ Bg,
                      float* __restrict__ Cg,
                      int K, int lda, int ldb, int ldc,
                      long aOff1, long bOff1, long cOff1, float alpha) {
    const float* A = Ag + (long)blockIdx.z * aOff1;
    const float* B = Bg + (long)blockIdx.z * bOff1;
    float* C = Cg + (long)blockIdx.z * cOff1;

    constexpr int AS_STRIDE = 36;      // 32 + 4 pad -> conflict-free frag loads
    constexpr int BS_STRIDE_NT = 36;
    constexpr int BS_STRIDE_NN = 136;  // 128 + 8 pad

    __shared__ uint32_t As[128 * AS_STRIDE];
    __shared__ uint32_t Bs[TRANSB ? 128 * BS_STRIDE_NT : 32 * BS_STRIDE_NN];

    const int tid = threadIdx.x;
    const int lane = tid & 31;
    const int warp = tid >> 5;
    const int g = lane >> 2;      // group id (0..7)
    const int tg = lane & 3;      // thread in group (0..3)
    const int wm = warp >> 1;     // 0..3  -> warp row * 32
    const int wn = warp & 1;      // 0..1  -> warp col * 64
    const int m0 = blockIdx.y * 128;
    const int n0 = blockIdx.x * 128;

    float acc[2][8][4] = {};

    for (int kt = 0; kt < K; kt += 32) {
        // ---- load A tile 128x32 -> As[m][k] (tf32 bits) ----
        // 1024 float4s, 8 float4s per row (32 cols / 4).
        #pragma unroll
        for (int i = 0; i < 4; i++) {
            int idx = tid + i * 256;
            int row = idx >> 3;          // m (0..127)
            int cv = (idx & 7) * 4;      // k
            float4 v = *reinterpret_cast<const float4*>(
                A + (long)(m0 + row) * lda + kt + cv);
            uint32_t* dst = &As[row * AS_STRIDE + cv];
            dst[0] = f2tf32(v.x); dst[1] = f2tf32(v.y);
            dst[2] = f2tf32(v.z); dst[3] = f2tf32(v.w);
        }
        // ---- load B tile ----
        if constexpr (TRANSB) {
            // B N x K: Bs[n][k], 128 rows x 32 cols, 8 float4s per row.
            #pragma unroll
            for (int i = 0; i < 4; i++) {
                int idx = tid + i * 256;
                int row = idx >> 3;      // n (0..127)
                int cv = (idx & 7) * 4;  // k
                float4 v = *reinterpret_cast<const float4*>(
                    B + (long)(n0 + row) * ldb + kt + cv);
                uint32_t* dst = &Bs[row * BS_STRIDE_NT + cv];
                dst[0] = f2tf32(v.x); dst[1] = f2tf32(v.y);
                dst[2] = f2tf32(v.z); dst[3] = f2tf32(v.w);
            }
        } else {
            // B K x N: Bs[k][n], 32 rows x 128 cols, 32 float4s per row.
            #pragma unroll
            for (int i = 0; i < 4; i++) {
                int idx = tid + i * 256;
                int row = idx >> 5;          // k (0..31)
                int cv = (idx & 31) * 4;     // n
                float4 v = *reinterpret_cast<const float4*>(
                    B + (long)(kt + row) * ldb + n0 + cv);
                uint32_t* dst = &Bs[row * BS_STRIDE_NN + cv];
                dst[0] = f2tf32(v.x); dst[1] = f2tf32(v.y);
                dst[2] = f2tf32(v.z); dst[3] = f2tf32(v.w);
            }
        }
        __syncthreads();

        #pragma unroll
        for (int ks = 0; ks < 4; ks++) {
            const int k0 = ks * 8;
            uint32_t af[2][4];
            #pragma unroll
            for (int mi = 0; mi < 2; mi++) {
                int rb = wm * 32 + mi * 16;
                af[mi][0] = As[(rb + g) * AS_STRIDE + k0 + tg];
                af[mi][1] = As[(rb + g + 8) * AS_STRIDE + k0 + tg];
                af[mi][2] = As[(rb + g) * AS_STRIDE + k0 + tg + 4];
                af[mi][3] = As[(rb + g + 8) * AS_STRIDE + k0 + tg + 4];
            }
            uint32_t bf[8][2];
            #pragma unroll
            for (int ni = 0; ni < 8; ni++) {
                int nb = wn * 64 + ni * 8;
                if constexpr (TRANSB) {
                    bf[ni][0] = Bs[(nb + g) * BS_STRIDE_NT + k0 + tg];
                    bf[ni][1] = Bs[(nb + g) * BS_STRIDE_NT + k0 + tg + 4];
                } else {
                    bf[ni][0] = Bs[(k0 + tg) * BS_STRIDE_NN + nb + g];
                    bf[ni][1] = Bs[(k0 + tg + 4) * BS_STRIDE_NN + nb + g];
                }
            }
            #pragma unroll
            for (int mi = 0; mi < 2; mi++)
                #pragma unroll
                for (int ni = 0; ni < 8; ni++) {
                    float* c = acc[mi][ni];
                    asm volatile(
                        "mma.sync.aligned.m16n8k8.row.col.f32.tf32.tf32.f32 "
                        "{%0,%1,%2,%3}, {%4,%5,%6,%7}, {%8,%9}, {%0,%1,%2,%3};"
                        : "+f"(c[0]), "+f"(c[1]), "+f"(c[2]), "+f"(c[3])
                        : "r"(af[mi][0]), "r"(af[mi][1]), "r"(af[mi][2]),
                          "r"(af[mi][3]), "r"(bf[ni][0]), "r"(bf[ni][1]));
                }
        }
        __syncthreads();
    }

    // ---- epilogue ----
    #pragma unroll
    for (int mi = 0; mi < 2; mi++) {
        int r0 = m0 + wm * 32 + mi * 16 + g;
        #pragma unroll
        for (int ni = 0; ni < 8; ni++) {
            int col = n0 + wn * 64 + ni * 8 + tg * 2;
            float2 v0 = {alpha * acc[mi][ni][0], alpha * acc[mi][ni][1]};
            float2 v1 = {alpha * acc[mi][ni][2], alpha * acc[mi][ni][3]};
            *reinterpret_cast<float2*>(C + (long)r0 * ldc + col) = v0;
            *reinterpret_cast<float2*>(C + (long)(r0 + 8) * ldc + col) = v1;
        }
    }
}

// ======================= fp32 SGEMM (small steps) ==========================
template <int BM, int BN, int BK, int TM, int TN, bool TRANSB>
__global__ __launch_bounds__((BM / TM) * (BN / TN))
void sgemm_kernel(const float* __restrict__ Ag, const float* __restrict__ Bg,
                  float* __restrict__ Cg,
                  int M, int N, int K, int lda, int ldb, int ldc,
                  long aOff1, long aOff2, long bOff1, long bOff2,
                  long cOff1, long cOff2, int Z2, float alpha) {
    constexpr int THREADS = (BM / TM) * (BN / TN);
    const int z = blockIdx.z;
    const int z1 = z / Z2;
    const int z2 = z - z1 * Z2;
    const float* A = Ag + (long)z1 * aOff1 + (long)z2 * aOff2;
    const float* B = Bg + (long)z1 * bOff1 + (long)z2 * bOff2;
    float* C = Cg + (long)z1 * cOff1 + (long)z2 * cOff2;

    __shared__ __align__(16) float As[BK][BM];
    __shared__ __align__(16) float Bs[BK][BN];

    const int tid = threadIdx.x;
    const int m0 = blockIdx.y * BM;
    const int n0 = blockIdx.x * BN;
    const int tm0 = (tid / (BN / TN)) * TM;
    const int tn0 = (tid % (BN / TN)) * TN;

    float acc[TM][TN] = {};

    constexpr int KV = BK / 4;
    constexpr int A_PER = (BM * KV) / THREADS;

    for (int kt = 0; kt < K; kt += BK) {
        #pragma unroll
        for (int i = 0; i < A_PER; i++) {
            int idx = tid + i * THREADS;
            int row = idx / KV;
            int cv = idx - row * KV;
            float4 v = *reinterpret_cast<const float4*>(
                A + (long)(m0 + row) * lda + kt + cv * 4);
            As[cv * 4 + 0][row] = v.x;
            As[cv * 4 + 1][row] = v.y;
            As[cv * 4 + 2][row] = v.z;
            As[cv * 4 + 3][row] = v.w;
        }
        if constexpr (TRANSB) {
            constexpr int B_PER = (BN * KV) / THREADS;
            #pragma unroll
            for (int i = 0; i < B_PER; i++) {
                int idx = tid + i * THREADS;
                int row = idx / KV;
                int cv = idx - row * KV;
                float4 v = *reinterpret_cast<const float4*>(
                    B + (long)(n0 + row) * ldb + kt + cv * 4);
                Bs[cv * 4 + 0][row] = v.x;
                Bs[cv * 4 + 1][row] = v.y;
                Bs[cv * 4 + 2][row] = v.z;
                Bs[cv * 4 + 3][row] = v.w;
            }
        } else {
            constexpr int NV = BN / 4;
            constexpr int B_PER = (BK * NV) / THREADS;
            #pragma unroll
            for (int i = 0; i < B_PER; i++) {
                int idx = tid + i * THREADS;
                int row = idx / NV;
                int cv = idx - row * NV;
                float4 v = *reinterpret_cast<const float4*>(
                    B + (long)(kt + row) * ldb + n0 + cv * 4);
                *reinterpret_cast<float4*>(&Bs[row][cv * 4]) = v;
            }
        }
        __syncthreads();

        #pragma unroll
        for (int kk = 0; kk < BK; kk++) {
            float ra[TM], rb[TN];
            #pragma unroll
            for (int i = 0; i < TM / 4; i++)
                *reinterpret_cast<float4*>(&ra[i * 4]) =
                    *reinterpret_cast<const float4*>(&As[kk][tm0 + i * 4]);
            #pragma unroll
            for (int j = 0; j < TN / 4; j++)
                *reinterpret_cast<float4*>(&rb[j * 4]) =
                    *reinterpret_cast<const float4*>(&Bs[kk][tn0 + j * 4]);
            #pragma unroll
            for (int i = 0; i < TM; i++)
                #pragma unroll
                for (int j = 0; j < TN; j++)
                    acc[i][j] = fmaf(ra[i], rb[j], acc[i][j]);
        }
        __syncthreads();
    }

    #pragma unroll
    for (int i = 0; i < TM; i++) {
        #pragma unroll
        for (int j = 0; j < TN / 4; j++) {
            float4 v;
            v.x = alpha * acc[i][j * 4 + 0];
            v.y = alpha * acc[i][j * 4 + 1];
            v.z = alpha * acc[i][j * 4 + 2];
            v.w = alpha * acc[i][j * 4 + 3];
            *reinterpret_cast<float4*>(
                C + (long)(m0 + tm0 + i) * ldc + n0 + tn0 + j * 4) = v;
        }
    }
}

// ======================= softmax ===========================================
__global__ __launch_bounds__(256) void softmax4096_kernel(float* __restrict__ S) {
    float* row = S + (size_t)blockIdx.x * 4096;
    const int tid = threadIdx.x;
    __shared__ float red[8];

    float4 v[4];
    float maxv = -3.4e38f;
    #pragma unroll
    for (int i = 0; i < 4; i++) {
        v[i] = reinterpret_cast<const float4*>(row)[tid + i * 256];
        maxv = fmaxf(maxv, fmaxf(fmaxf(v[i].x, v[i].y), fmaxf(v[i].z, v[i].w)));
    }
    #pragma unroll
    for (int o = 16; o > 0; o >>= 1)
        maxv = fmaxf(maxv, __shfl_xor_sync(0xffffffffu, maxv, o));
    if ((tid & 31) == 0) red[tid >> 5] = maxv;
    __syncthreads();
    float bm = red[0];
    #pragma unroll
    for (int i = 1; i < 8; i++) bm = fmaxf(bm, red[i]);

    float sum = 0.f;
    #pragma unroll
    for (int i = 0; i < 4; i++) {
        v[i].x = __expf(v[i].x - bm);
        v[i].y = __expf(v[i].y - bm);
        v[i].z = __expf(v[i].z - bm);
        v[i].w = __expf(v[i].w - bm);
        sum += (v[i].x + v[i].y) + (v[i].z + v[i].w);
    }
    __syncthreads();
    #pragma unroll
    for (int o = 16; o > 0; o >>= 1) sum += __shfl_xor_sync(0xffffffffu, sum, o);
    if ((tid & 31) == 0) red[tid >> 5] = sum;
    __syncthreads();
    float tot = 0.f;
    #pragma unroll
    for (int i = 0; i < 8; i++) tot += red[i];
    const float inv = 1.0f / tot;
    #pragma unroll
    for (int i = 0; i < 4; i++) {
        v[i].x *= inv; v[i].y *= inv; v[i].z *= inv; v[i].w *= inv;
        reinterpret_cast<float4*>(row)[tid + i * 256] = v[i];
    }
}

extern "C" void kernel_launch(void* const* d_in, const int* in_sizes, int n_in,
                              void* d_out, int out_size) {
    const float* img = (const float*)d_in[0];  // (16,4096,1024)
    const float* aud = (const float*)d_in[1];  // (16,64,1024)
    const float* Wq = (const float*)d_in[2];   // (1024,1024)
    const float* Wk = (const float*)d_in[3];
    const float* Wv = (const float*)d_in[4];
    float* out = (float*)d_out;                // (16,64,1024)

    float *q, *qt, *sc, *t;
    cudaGetSymbolAddress((void**)&q, g_q);
    cudaGetSymbolAddress((void**)&qt, g_qt);
    cudaGetSymbolAddress((void**)&sc, g_sc);
    cudaGetSymbolAddress((void**)&t, g_t);

    const float scale = 0.08838834764831845f;  // (1024/8)^-0.5

    // 1) q = aud @ Wq^T : M=1024, N=1024, K=1024  (tf32, NT)
    tf32_gemm_kernel<true><<<dim3(8, 8, 1), 256>>>(
        aud, Wq, q, 1024, 1024, 1024, 1024, 0, 0, 0, 1.0f);

    // 2) qt[b,h] = Q_bh @ Wk_h : M=64, N=1024, K=128, z = b*8+h (fp32, NN)
    sgemm_kernel<64, 64, 16, 4, 4, false><<<dim3(16, 1, 128), 256>>>(
        q, Wk, qt, 64, 1024, 128, 1024, 1024, 1024,
        65536, 128, 0, 131072, 524288, 65536, 8, 1.0f);

    // 3) sc_b = qt_b @ img_b^T * scale : M=512, N=4096, K=1024 (tf32, NT)
    tf32_gemm_kernel<true><<<dim3(32, 4, 16), 256>>>(
        qt, img, sc, 1024, 1024, 1024, 4096,
        524288, 4194304, 2097152, scale);

    // 4) softmax over the 4096-wide rows (16*512 rows)
    softmax4096_kernel<<<16 * 512, 256>>>(sc);

    // 5) t_b = P_b @ img_b : M=512, N=1024, K=4096 (tf32, NN)
    tf32_gemm_kernel<false><<<dim3(8, 4, 16), 256>>>(
        sc, img, t, 4096, 4096, 1024, 1024,
        2097152, 4194304, 524288, 1.0f);

    // 6) out[b,:,h*128:(h+1)*128] = t_bh @ Wv_h^T : M=64, N=128, K=1024 (fp32, NT)
    sgemm_kernel<64, 64, 16, 4, 4, true><<<dim3(2, 1, 128), 256>>>(
        t, Wv, out, 64, 128, 1024, 1024, 1024, 1024,
        524288, 65536, 0, 131072, 65536, 128, 8, 1.0f);
}